// round 4
// baseline (speedup 1.0000x reference)
#include <cuda_runtime.h>
#include <math.h>

#define ACC_CAP     (1 << 21)
#define LIST_CAP    (1 << 20)
#define BLOOM_WORDS 256            // 8192 bits
#define BLOOM_MASK  8191u

__device__ float    g_acc[ACC_CAP];   // zero-init; fix phase restores zeros
__device__ int2     g_list[LIST_CAP];
__device__ int      g_cnt;            // reset by fix phase
__device__ unsigned g_done;           // reset by fix phase

__device__ __forceinline__ float final_elem(float a1, float a2)
{
    float t1 = 1.0f / (1.0f + __expf(-a1));
    float t2 = 1.0f / (1.0f + __expf(-a2));
    float tp = t1 * t2;
    const float EPS = 1e-10f;
    return __logf((tp + EPS) / (1.0f - tp + EPS));
}

__global__ void k_all(const int* __restrict__ e_index,
                      const int* __restrict__ r_index,
                      const int* __restrict__ edge_index,
                      const int* __restrict__ edge_type,
                      const float* __restrict__ rel_emb,
                      const float* __restrict__ rel_proj,
                      const float* __restrict__ w_out,
                      float* __restrict__ out,
                      int E, int nBQ, int D, int N, int outN, int scatBlocks)
{
    int tid = threadIdx.x;
    int bid = blockIdx.x;

    if (bid < scatBlocks) {
        // ---- edge scan with shared bloom filter, 4 edges/thread ----
        __shared__ int s_e[64];
        __shared__ int s_r[64];
        __shared__ unsigned s_bloom[BLOOM_WORDS];
        if (tid < BLOOM_WORDS) s_bloom[tid] = 0u;
        __syncthreads();
        if (tid < nBQ) {
            int ev = e_index[tid];
            s_e[tid] = ev;
            s_r[tid] = r_index[tid];
            unsigned h = (unsigned)ev & BLOOM_MASK;
            atomicOr(&s_bloom[h >> 5], 1u << (h & 31u));
        }
        __syncthreads();

        int base = (bid * blockDim.x + tid) * 4;
        int srcs[4];
        if (base + 3 < E) {
            int4 sv = *(const int4*)(edge_index + base);
            srcs[0] = sv.x; srcs[1] = sv.y; srcs[2] = sv.z; srcs[3] = sv.w;
        } else {
            #pragma unroll
            for (int j = 0; j < 4; j++)
                srcs[j] = (base + j < E) ? edge_index[base + j] : -1;
        }

        int lane = tid & 31;
        #pragma unroll
        for (int j = 0; j < 4; j++) {
            int src = srcs[j];
            bool maybe = false;
            if (src >= 0) {
                unsigned h = (unsigned)src & BLOOM_MASK;
                maybe = (s_bloom[h >> 5] >> (h & 31u)) & 1u;
            }
            unsigned cand = __ballot_sync(0xFFFFFFFFu, maybe);
            if (!cand) continue;

            // exact check only for candidates (bloom FPs drop out here)
            unsigned long long mm = 0ull;
            if (maybe) {
                for (int bq = 0; bq < nBQ; bq++)
                    mm |= ((unsigned long long)(src == s_e[bq])) << bq;
            }
            unsigned any = __ballot_sync(0xFFFFFFFFu, mm != 0ull);
            while (any) {
                int leader = __ffs(any) - 1;
                any &= any - 1;
                unsigned long long lm = __shfl_sync(0xFFFFFFFFu, mm, leader);
                int le = __shfl_sync(0xFFFFFFFFu, base, leader) + j;
                int t   = edge_type[le];
                int dst = edge_index[E + le];
                const float* pt = rel_proj + (size_t)t * D;
                while (lm) {
                    int bq = __ffsll(lm) - 1;
                    lm &= lm - 1;
                    const float* pr = rel_emb + (size_t)s_r[bq] * D;
                    float s = 0.0f;
                    for (int d = lane; d < D; d += 32)
                        s += pr[d] * w_out[d] * pt[d];
                    #pragma unroll
                    for (int o = 16; o > 0; o >>= 1)
                        s += __shfl_xor_sync(0xFFFFFFFFu, s, o);
                    if (lane == 0) {
                        atomicAdd(&g_acc[(size_t)bq * N + dst], s);
                        int idx = atomicAdd(&g_cnt, 1);
                        if (idx < LIST_CAP) g_list[idx] = make_int2(bq, dst);
                    }
                }
            }
        }
    } else {
        // ---- const fill of out ----
        float cv = final_elem(0.0f, 0.0f);
        int i  = (bid - scatBlocks) * blockDim.x + tid;
        int n4 = outN >> 2;
        if (i < n4) ((float4*)out)[i] = make_float4(cv, cv, cv, cv);
        int tail = outN & 3;
        if (i < tail) out[(n4 << 2) + i] = cv;
    }

    // ---- last block performs the sparse fix-up ----
    __threadfence();
    __shared__ bool isLast;
    if (tid == 0)
        isLast = (atomicAdd(&g_done, 1u) == (unsigned)gridDim.x - 1u);
    __syncthreads();
    if (!isLast) return;
    __threadfence();

    int cnt = atomicAdd(&g_cnt, 0);
    if (cnt > LIST_CAP) cnt = LIST_CAP;

    for (int i = tid; i < cnt; i += blockDim.x) {
        int2 en = g_list[i];
        int b = en.x >> 1, n = en.y;
        float a1 = g_acc[(size_t)(2 * b)     * N + n];
        float a2 = g_acc[(size_t)(2 * b + 1) * N + n];
        out[(size_t)b * N + n] = final_elem(a1, a2);
    }
    __syncthreads();
    for (int i = tid; i < cnt; i += blockDim.x) {
        int2 en = g_list[i];
        int b = en.x >> 1, n = en.y;
        g_acc[(size_t)(2 * b)     * N + n] = 0.0f;
        g_acc[(size_t)(2 * b + 1) * N + n] = 0.0f;
    }
    __syncthreads();
    if (tid == 0) { g_cnt = 0; g_done = 0u; }
}

extern "C" void kernel_launch(void* const* d_in, const int* in_sizes, int n_in,
                              void* d_out, int out_size)
{
    // Input order: e_index, r_index, edge_index, edge_type, [num_nodes], rel_emb, rel_proj, w_out
    const int* e_index    = (const int*)d_in[0];
    const int* r_index    = (const int*)d_in[1];
    const int* edge_index = (const int*)d_in[2];
    const int* edge_type  = (const int*)d_in[3];
    int off = (n_in >= 8) ? 5 : 4;
    const float* rel_emb  = (const float*)d_in[off];
    const float* rel_proj = (const float*)d_in[off + 1];
    const float* w_out    = (const float*)d_in[off + 2];

    int nBQ = in_sizes[0];               // B*2
    int B   = nBQ / 2;
    int E   = in_sizes[3];               // edge_type is [E]
    int D   = in_sizes[off + 2];         // w_out is [D]
    int N   = out_size / B;              // output is [B, N]
    int outN = out_size;

    const int TPB = 256;
    int scatBlocks = (E + TPB * 4 - 1) / (TPB * 4);
    int fillBlocks = ((outN >> 2) + TPB - 1) / TPB + 1;
    int grid = scatBlocks + fillBlocks;

    k_all<<<grid, TPB>>>(e_index, r_index, edge_index, edge_type,
                         rel_emb, rel_proj, w_out, (float*)d_out,
                         E, nBQ, D, N, outN, scatBlocks);
}